// round 6
// baseline (speedup 1.0000x reference)
#include <cuda_runtime.h>

// Sinkhorn: 65536 matrices of 36x36, 21 iterations of row/col log-normalization,
// temperature 0.01, output exp(log_alpha). Base-2 potential form:
//   matrix = y - U_i - V_j,  y = input * (100*log2 e)
//   row pass: U_i = lse2_j(y_ij - V_j);  col pass: V_j = lse2_i(y_ij - U_i)
//
// R6: (a) no max pre-pass — shift lse by the thread's PREVIOUS potential
// (lse is shift-invariant; window-check s in (2^-100, 2^100) with exact-max
// fallback for the rare over/underflow). (b) MUFU/FMA pipe split: 8 of 36
// exps per pass computed by an FMA-pipe polynomial exp2, cutting the binding
// MUFU pipe from 37 to 29 ops/pass.

#define NMAT_PER_BLOCK 8
#define THREADS 288            // 8 groups * 36 = 9 full warps
#define NDIM 36
#define STRIDE 37              // conflict-free rows & columns
#define MAT_SMEM (NDIM * STRIDE)
#define MAT_ELEMS (NDIM * NDIM)
#define SCALE 144.269504088896340736f   // 100 * log2(e)
#define NITERS 21
#define NSOFT 8                // exps routed to the FMA pipe per pass
#define MAGIC 12582912.0f      // 1.5 * 2^23
#define WIN_LO 7.8886e-31f     // 2^-100
#define WIN_HI 1.2677e+30f     // 2^100

__device__ __forceinline__ float ex2f(float x) {
    float y; asm("ex2.approx.ftz.f32 %0, %1;" : "=f"(y) : "f"(x)); return y;
}
__device__ __forceinline__ float lg2f(float x) {
    float y; asm("lg2.approx.ftz.f32 %0, %1;" : "=f"(y) : "f"(x)); return y;
}

// FMA-pipe exp2. Valid for x >= -126 (clamped); for x > ~127 it produces
// garbage whose magnitude/sign fails the caller's window check -> exact
// fallback. Max rel err ~2.4e-6 (degree-5 Taylor on [-0.5, 0.5]).
__device__ __forceinline__ float soft_ex2(float x) {
    x = fmaxf(x, -126.0f);
    float t = __fadd_rn(x, MAGIC);           // rint(x) encoded in mantissa
    float n = __fadd_rn(t, -MAGIC);          // rint(x) as float
    float f = x - n;                         // [-0.5, 0.5]
    float p =            1.3333558e-3f;
    p = __fmaf_rn(p, f, 9.6181291e-3f);
    p = __fmaf_rn(p, f, 5.5504109e-2f);
    p = __fmaf_rn(p, f, 2.4022651e-1f);
    p = __fmaf_rn(p, f, 6.9314718e-1f);
    p = __fmaf_rn(p, f, 1.0f);
    // bits(t) = 0x4B400000 + n; low 9 bits of 0x4B400000 are 0, so
    // (bits(t) << 23) == n << 23 exactly (mod 2^32): exponent splice.
    return __int_as_float(__float_as_int(p) + (__float_as_int(t) << 23));
}

__device__ __forceinline__ bool in_window(float s) {
    return (s > WIN_LO) && (s < WIN_HI);     // false for 0, inf, NaN, negative
}

__global__ __launch_bounds__(THREADS, 3)
void sinkhorn_kernel(const float* __restrict__ in, float* __restrict__ out)
{
    __shared__ float sy[NMAT_PER_BLOCK * MAT_SMEM];
    __shared__ __align__(16) float sU[NMAT_PER_BLOCK * NDIM];
    __shared__ __align__(16) float sV[NMAT_PER_BLOCK * NDIM];

    const int tid = threadIdx.x;
    const long long base = (long long)blockIdx.x * (NMAT_PER_BLOCK * MAT_ELEMS);

    // ---- load: coalesced float4, scatter into padded smem, fused base-2 scale
    {
        const float4* in4 = (const float4*)(in + base);
        for (int k = tid; k < (NMAT_PER_BLOCK * MAT_ELEMS) / 4; k += THREADS) {
            float4 v = in4[k];
            float vals[4] = {v.x, v.y, v.z, v.w};
            int e = k * 4;
            #pragma unroll
            for (int q = 0; q < 4; q++) {
                int idx = e + q;
                int gg  = idx / MAT_ELEMS;
                int rem = idx - gg * MAT_ELEMS;
                int r   = rem / NDIM;
                int c   = rem - r * NDIM;
                sy[gg * MAT_SMEM + r * STRIDE + c] = vals[q] * SCALE;
            }
        }
    }
    sV[tid] = 0.0f;                          // 288 == THREADS
    __syncthreads();

    const int g = tid / NDIM;
    const int l = tid - g * NDIM;

    float* U = &sU[g * NDIM];
    float* V = &sV[g * NDIM];
    const float* srow = &sy[g * MAT_SMEM + l * STRIDE];
    const float* scol = &sy[g * MAT_SMEM + l];

    // my row in registers; mx0 = exact row max (V=0 -> exact shift at iter 0)
    float yreg[NDIM];
    float mx0 = -3.0e38f;
    #pragma unroll
    for (int j = 0; j < NDIM; j++) { yreg[j] = srow[j]; mx0 = fmaxf(mx0, yreg[j]); }

    float uown = mx0;      // previous row potential (lse shift)
    float vown = 0.0f;     // previous col potential

    #pragma unroll 1
    for (int it = 0; it < NITERS; it++) {
        // ================= row pass: U[l] = lse2_j(yreg[j] - V[j]) =================
        {
            float m = uown;
            float a0 = 0.f, a1 = 0.f;                    // soft accumulators
            #pragma unroll
            for (int j = 0; j < NSOFT; j += 2) {
                a0 += soft_ex2((yreg[j]   - m) - V[j]);
                a1 += soft_ex2((yreg[j+1] - m) - V[j+1]);
            }
            float s0 = 0.f, s1 = 0.f, s2 = 0.f, s3 = 0.f; // MUFU accumulators
            #pragma unroll
            for (int j = NSOFT; j < NDIM; j += 4) {
                s0 += ex2f((yreg[j]   - m) - V[j]);
                s1 += ex2f((yreg[j+1] - m) - V[j+1]);
                s2 += ex2f((yreg[j+2] - m) - V[j+2]);
                s3 += ex2f((yreg[j+3] - m) - V[j+3]);
            }
            float s = ((a0 + a1) + (s0 + s1)) + (s2 + s3);
            if (!in_window(s)) {
                // exact fallback: true max shift, all-MUFU sum (rare)
                m = -3.0e38f;
                #pragma unroll
                for (int j = 0; j < NDIM; j++) m = fmaxf(m, yreg[j] - V[j]);
                s = 0.f;
                #pragma unroll
                for (int j = 0; j < NDIM; j++) s += ex2f((yreg[j] - m) - V[j]);
            }
            uown = m + lg2f(s);
            U[l] = uown;
        }
        __syncthreads();

        // ================= col pass: V[l] = lse2_i(y[i][l] - U[i]) =================
        {
            float m = vown;
            float a0 = 0.f, a1 = 0.f;
            #pragma unroll
            for (int i = 0; i < NSOFT; i += 2) {
                a0 += soft_ex2((scol[(i)   * STRIDE] - m) - U[i]);
                a1 += soft_ex2((scol[(i+1) * STRIDE] - m) - U[i+1]);
            }
            float s0 = 0.f, s1 = 0.f, s2 = 0.f, s3 = 0.f;
            #pragma unroll
            for (int i = NSOFT; i < NDIM; i += 4) {
                s0 += ex2f((scol[(i)   * STRIDE] - m) - U[i]);
                s1 += ex2f((scol[(i+1) * STRIDE] - m) - U[i+1]);
                s2 += ex2f((scol[(i+2) * STRIDE] - m) - U[i+2]);
                s3 += ex2f((scol[(i+3) * STRIDE] - m) - U[i+3]);
            }
            float s = ((a0 + a1) + (s0 + s1)) + (s2 + s3);
            if (!in_window(s)) {
                m = -3.0e38f;
                #pragma unroll
                for (int i = 0; i < NDIM; i++) m = fmaxf(m, scol[i * STRIDE] - U[i]);
                s = 0.f;
                #pragma unroll
                for (int i = 0; i < NDIM; i++) s += ex2f((scol[i * STRIDE] - m) - U[i]);
            }
            vown = m + lg2f(s);
            V[l] = vown;
        }
        __syncthreads();
    }

    // ---- output: overwrite sy with 2^(y - U - V), then coalesced float4 store
    {
        float* od = &sy[g * MAT_SMEM + l * STRIDE];
        #pragma unroll
        for (int j = 0; j < NDIM; j++) {
            od[j] = ex2f((yreg[j] - uown) - V[j]);
        }
    }
    __syncthreads();
    {
        float4* out4 = (float4*)(out + base);
        for (int k = tid; k < (NMAT_PER_BLOCK * MAT_ELEMS) / 4; k += THREADS) {
            int e = k * 4;
            float r[4];
            #pragma unroll
            for (int q = 0; q < 4; q++) {
                int idx = e + q;
                int gg  = idx / MAT_ELEMS;
                int rem = idx - gg * MAT_ELEMS;
                int rr  = rem / NDIM;
                int cc  = rem - rr * NDIM;
                r[q] = sy[gg * MAT_SMEM + rr * STRIDE + cc];
            }
            out4[k] = make_float4(r[0], r[1], r[2], r[3]);
        }
    }
}

extern "C" void kernel_launch(void* const* d_in, const int* in_sizes, int n_in,
                              void* d_out, int out_size) {
    const float* in = (const float*)d_in[0];
    float* out = (float*)d_out;
    int num_mats = in_sizes[0] / MAT_ELEMS;          // 65536
    int grid = num_mats / NMAT_PER_BLOCK;            // 8192
    sinkhorn_kernel<<<grid, THREADS>>>(in, out);
}